// round 1
// baseline (speedup 1.0000x reference)
#include <cuda_runtime.h>
#include <math.h>

#define LQ 8192
#define LK 8192
#define DIM 128
#define KCHUNKS 8
#define SCALE 0.08838834764831845f  // 1/sqrt(128)

// scratch (no allocations allowed -> device globals)
__device__ float g_m[LQ];
__device__ float g_l[LQ];
__device__ float g_opart[(size_t)KCHUNKS * LQ * DIM];

// ---------------------------------------------------------------------------
// Kernel A: S = Q @ K^T * scale, written to att region.
// 128x128 block tile, 256 threads, 8x8 micro-tile with 16-strided ownership
// (conflict-free LDS in the main loop). Smem holds d-major (transposed) tiles.
// ---------------------------------------------------------------------------
__global__ __launch_bounds__(256) void qk_kernel(const float* __restrict__ Q,
                                                 const float* __restrict__ K,
                                                 float* __restrict__ S) {
    extern __shared__ float sm[];
    float* Qs = sm;               // [128 d][129] -> Qs[d*129 + m]
    float* Ks = sm + 128 * 129;   // [128 d][129] -> Ks[d*129 + n]

    const int tid = threadIdx.x;
    const int m0 = blockIdx.y * 128;
    const int n0 = blockIdx.x * 128;

    // load + transpose tiles into smem (one-time; 4-way store conflicts OK)
#pragma unroll
    for (int i = 0; i < 16; i++) {
        int f4 = i * 256 + tid;      // 0..4095
        int row = f4 >> 5;           // 0..127
        int c4 = f4 & 31;            // 0..31
        float4 q = *(const float4*)(Q + (size_t)(m0 + row) * DIM + c4 * 4);
        float4 k = *(const float4*)(K + (size_t)(n0 + row) * DIM + c4 * 4);
        Qs[(c4 * 4 + 0) * 129 + row] = q.x;
        Qs[(c4 * 4 + 1) * 129 + row] = q.y;
        Qs[(c4 * 4 + 2) * 129 + row] = q.z;
        Qs[(c4 * 4 + 3) * 129 + row] = q.w;
        Ks[(c4 * 4 + 0) * 129 + row] = k.x;
        Ks[(c4 * 4 + 1) * 129 + row] = k.y;
        Ks[(c4 * 4 + 2) * 129 + row] = k.z;
        Ks[(c4 * 4 + 3) * 129 + row] = k.w;
    }
    __syncthreads();

    const int tr = tid >> 4;   // 0..15 row group
    const int tc = tid & 15;   // 0..15 col group
    float acc[8][8];
#pragma unroll
    for (int i = 0; i < 8; i++)
#pragma unroll
        for (int j = 0; j < 8; j++) acc[i][j] = 0.f;

#pragma unroll 4
    for (int kk = 0; kk < DIM; kk++) {
        float a[8], b[8];
#pragma unroll
        for (int i = 0; i < 8; i++) a[i] = Qs[kk * 129 + tr + 16 * i];
#pragma unroll
        for (int j = 0; j < 8; j++) b[j] = Ks[kk * 129 + tc + 16 * j];
#pragma unroll
        for (int i = 0; i < 8; i++)
#pragma unroll
            for (int j = 0; j < 8; j++) acc[i][j] += a[i] * b[j];
    }

#pragma unroll
    for (int i = 0; i < 8; i++) {
        size_t rbase = (size_t)(m0 + tr + 16 * i) * LK + n0;
#pragma unroll
        for (int j = 0; j < 8; j++) {
            S[rbase + tc + 16 * j] = acc[i][j] * SCALE;
        }
    }
}

// ---------------------------------------------------------------------------
// Kernel B: per-row max and sum(exp(s - max)). One block per query row.
// Row data kept in registers (32 floats/thread), reduced via smem.
// ---------------------------------------------------------------------------
__global__ __launch_bounds__(256) void stats_kernel(const float* __restrict__ S) {
    __shared__ float red[256];
    const int tid = threadIdx.x;
    const size_t row = blockIdx.x;
    const float4* src = (const float4*)(S + row * LK);

    float4 v[8];
    float lm = -1e30f;
#pragma unroll
    for (int i = 0; i < 8; i++) {
        v[i] = src[i * 256 + tid];
        lm = fmaxf(lm, fmaxf(fmaxf(v[i].x, v[i].y), fmaxf(v[i].z, v[i].w)));
    }
    red[tid] = lm;
    __syncthreads();
    for (int s = 128; s > 0; s >>= 1) {
        if (tid < s) red[tid] = fmaxf(red[tid], red[tid + s]);
        __syncthreads();
    }
    const float m = red[0];
    __syncthreads();

    float ls = 0.f;
#pragma unroll
    for (int i = 0; i < 8; i++) {
        ls += __expf(v[i].x - m) + __expf(v[i].y - m) +
              __expf(v[i].z - m) + __expf(v[i].w - m);
    }
    red[tid] = ls;
    __syncthreads();
    for (int s = 128; s > 0; s >>= 1) {
        if (tid < s) red[tid] += red[tid + s];
        __syncthreads();
    }
    if (tid == 0) {
        g_m[row] = m;
        g_l[row] = red[0];
    }
}

// ---------------------------------------------------------------------------
// Kernel C: att = exp(S - m) / l  (in-place over the S values), fused with
// partial O += att @ V. Grid (KCHUNKS, LQ/128); each block owns a 128-row
// q-tile and a 1024-wide k-chunk; partial O goes to g_opart (deterministic).
// ---------------------------------------------------------------------------
__global__ __launch_bounds__(256) void softmax_pv_kernel(const float* __restrict__ V,
                                                         float* __restrict__ att) {
    extern __shared__ float sm[];
    float* Ps = sm;                 // [64 k][129] -> Ps[k*129 + qrow]
    float* Vs = sm + 64 * 129;      // [64 k][128] -> Vs[k*128 + dcol]
    float* mrow = Vs + 64 * 128;    // [128]
    float* ilrow = mrow + 128;      // [128]

    const int tid = threadIdx.x;
    const int q0 = blockIdx.y * 128;
    const int kstart = blockIdx.x * (LK / KCHUNKS);

    if (tid < 128) {
        mrow[tid] = g_m[q0 + tid];
        ilrow[tid] = 1.0f / g_l[q0 + tid];
    }
    __syncthreads();

    const int tr = tid >> 4;
    const int tc = tid & 15;
    float acc[8][8];
#pragma unroll
    for (int i = 0; i < 8; i++)
#pragma unroll
        for (int j = 0; j < 8; j++) acc[i][j] = 0.f;

    for (int t = 0; t < (LK / KCHUNKS) / 64; t++) {
        const int kb = kstart + t * 64;

        // load V tile [64][128]
#pragma unroll
        for (int i = 0; i < 8; i++) {
            int f4 = i * 256 + tid;
            int row = f4 >> 5;
            int c4 = f4 & 31;
            *(float4*)(Vs + row * 128 + c4 * 4) =
                *(const float4*)(V + (size_t)(kb + row) * DIM + c4 * 4);
        }

        // S tile [128 q][64 k]: read, softmax-normalize, write back, stage
        // transposed into Ps
#pragma unroll
        for (int i = 0; i < 8; i++) {
            int f4 = i * 256 + tid;
            int row = f4 >> 4;   // q row 0..127
            int c4 = f4 & 15;    // k group 0..15
            float* gp = att + (size_t)(q0 + row) * LK + kb + c4 * 4;
            float4 s = *(const float4*)gp;
            const float m = mrow[row];
            const float il = ilrow[row];
            float4 p;
            p.x = __expf(s.x - m) * il;
            p.y = __expf(s.y - m) * il;
            p.z = __expf(s.z - m) * il;
            p.w = __expf(s.w - m) * il;
            *(float4*)gp = p;
            Ps[(c4 * 4 + 0) * 129 + row] = p.x;
            Ps[(c4 * 4 + 1) * 129 + row] = p.y;
            Ps[(c4 * 4 + 2) * 129 + row] = p.z;
            Ps[(c4 * 4 + 3) * 129 + row] = p.w;
        }
        __syncthreads();

        // O += P @ V over this 64-wide k tile
#pragma unroll 2
        for (int kk = 0; kk < 64; kk++) {
            float a[8], b[8];
#pragma unroll
            for (int i = 0; i < 8; i++) a[i] = Ps[kk * 129 + tr + 16 * i];
#pragma unroll
            for (int j = 0; j < 8; j++) b[j] = Vs[kk * 128 + tc + 16 * j];
#pragma unroll
            for (int i = 0; i < 8; i++)
#pragma unroll
                for (int j = 0; j < 8; j++) acc[i][j] += a[i] * b[j];
        }
        __syncthreads();
    }

    float* op = g_opart + (size_t)blockIdx.x * ((size_t)LQ * DIM);
#pragma unroll
    for (int i = 0; i < 8; i++) {
        size_t rbase = (size_t)(q0 + tr + 16 * i) * DIM;
#pragma unroll
        for (int j = 0; j < 8; j++) {
            op[rbase + tc + 16 * j] = acc[i][j];
        }
    }
}

// ---------------------------------------------------------------------------
// Kernel D: reduce KCHUNKS partials into out.
// ---------------------------------------------------------------------------
__global__ __launch_bounds__(256) void reduce_kernel(float* __restrict__ out) {
    const size_t i = (size_t)blockIdx.x * 256 + threadIdx.x;
    float s = 0.f;
#pragma unroll
    for (int c = 0; c < KCHUNKS; c++) s += g_opart[(size_t)c * LQ * DIM + i];
    out[i] = s;
}

// ---------------------------------------------------------------------------
extern "C" void kernel_launch(void* const* d_in, const int* in_sizes, int n_in,
                              void* d_out, int out_size) {
    const float* Q = (const float*)d_in[0];
    const float* K = (const float*)d_in[1];
    const float* V = (const float*)d_in[2];
    float* out = (float*)d_out;                    // [LQ, DIM]
    float* att = out + (size_t)LQ * DIM;           // [LQ, LK]

    const int smemA = 2 * 128 * 129 * sizeof(float);                    // 132096
    const int smemC = (64 * 129 + 64 * 128 + 256) * sizeof(float);      // 66816
    cudaFuncSetAttribute(qk_kernel, cudaFuncAttributeMaxDynamicSharedMemorySize, smemA);
    cudaFuncSetAttribute(softmax_pv_kernel, cudaFuncAttributeMaxDynamicSharedMemorySize, smemC);

    qk_kernel<<<dim3(LK / 128, LQ / 128), 256, smemA>>>(Q, K, att);
    stats_kernel<<<LQ, 256>>>(att);
    softmax_pv_kernel<<<dim3(KCHUNKS, LQ / 128), 256, smemC>>>(V, att);
    reduce_kernel<<<(LQ * DIM) / 256, 256>>>(out);
}